// round 7
// baseline (speedup 1.0000x reference)
#include <cuda_runtime.h>

// ---------------------------------------------------------------------------
// QuantumDecoder: z -> tanh(z@W_in) -> 4-qubit circuit Z-expectations ->
//                 relu(@W1) -> sigmoid(@W2)
//
// Post-RY circuit is a fixed 16x16 unitary M:
//   z_q = s0^T Re(M^H Z_q M) s0 = sum_{i<=j} S_q[i,j] s_i s_j.
//
// R7:
//  K1 (front): 256 thr/block, 2 lanes per row. Fused per-block sim of the
//     16 basis columns -> S table. Dot packed f32x2 + split k-halves (shfl
//     reduce); quadratic forms split 2 q's per lane; exp-form fast tanh.
//  K2 (gemm): 2 output cols per thread (392 of 416 active), W2 in 8 packed
//     regs -> 39 warps/SM. h staged in smem, broadcast LDS, float2 stores.
// ---------------------------------------------------------------------------

__device__ unsigned long long g_h2[65536 * 8];         // h duplicated as f32x2

// ---- packed f32x2 helpers (Blackwell) -------------------------------------
__device__ __forceinline__ unsigned long long pack2(float x, float y) {
    unsigned long long r;
    asm("mov.b64 %0, {%1, %2};" : "=l"(r) : "f"(x), "f"(y));
    return r;
}
__device__ __forceinline__ void unpack2(unsigned long long v, float& x, float& y) {
    asm("mov.b64 {%0, %1}, %2;" : "=f"(x), "=f"(y) : "l"(v));
}
__device__ __forceinline__ unsigned long long ffma2(unsigned long long a,
                                                    unsigned long long b,
                                                    unsigned long long c) {
    unsigned long long d;
    asm("fma.rn.f32x2 %0, %1, %2, %3;" : "=l"(d) : "l"(a), "l"(b), "l"(c));
    return d;
}
__device__ __forceinline__ float sigmoidf_fast(float x) {
    float e = __expf(-x);                 // MUFU.EX2 path
    return __fdividef(1.0f, 1.0f + e);    // MUFU.RCP path
}
__device__ __forceinline__ float tanhf_fast(float x) {
    x = fminf(fmaxf(x, -15.f), 15.f);     // guard exp overflow -> NaN
    float e = __expf(-2.f * x);
    return __fdividef(1.f - e, 1.f + e);
}

// ---------------------------------------------------------------------------
// K1: front-end. 128 rows/block, 2 lanes (c = tid&1) per row.
// ---------------------------------------------------------------------------
__global__ void __launch_bounds__(256, 4) qd_front_kernel(
    const float* __restrict__ z,   const float* __restrict__ W_in,
    const float* __restrict__ b_in, const float* __restrict__ theta,
    const float* __restrict__ W1,  const float* __restrict__ b1)
{
    __shared__ ulonglong2 sWin2[128];   // W_in row k: packed (w0,w1),(w2,w3)
    __shared__ float2 sM[16][16];       // sM[x][j] = <x| fixed-circuit |j>
    __shared__ float  sS[136 * 4];      // pair coeffs, layout [pair][q]
    __shared__ float  sW1[32];          // W1 [4][8]
    __shared__ float  sb1[8];
    __shared__ float  sbin[4];

    int tid = threadIdx.x;
    if (tid < 128) {
        float4 wv = ((const float4*)W_in)[tid];
        sWin2[tid] = make_ulonglong2(pack2(wv.x, wv.y), pack2(wv.z, wv.w));
    }
    if (tid < 32) sW1[tid] = W1[tid];
    if (tid < 8)  sb1[tid] = b1[tid];
    if (tid < 4)  sbin[tid] = b_in[tid];

    // ---- per-block sim of the fixed circuit on basis state |tid> ----------
    if (tid < 16) {
        float2 st[16];
#pragma unroll
        for (int x = 0; x < 16; x++) st[x] = make_float2(0.f, 0.f);
        st[tid] = make_float2(1.f, 0.f);

#pragma unroll
        for (int layer = 0; layer < 2; layer++) {
#pragma unroll
            for (int q = 0; q < 4; q++) {
                float th = theta[layer * 4 + q];
                float ch, sh;
                __sincosf(0.5f * th, &sh, &ch);
                int bit = 1 << q;
#pragma unroll
                for (int a = 0; a < 8; a++) {
                    int i0 = ((a >> q) << (q + 1)) | (a & (bit - 1));
                    int i1 = i0 | bit;
                    float2 x0 = st[i0], x1 = st[i1];
                    // Rx
                    float2 y0 = make_float2(ch * x0.x + sh * x1.y, ch * x0.y - sh * x1.x);
                    float2 y1 = make_float2(ch * x1.x + sh * x0.y, ch * x1.y - sh * x0.x);
                    // Ry
                    float2 z0 = make_float2(ch * y0.x - sh * y1.x, ch * y0.y - sh * y1.y);
                    float2 z1 = make_float2(sh * y0.x + ch * y1.x, sh * y0.y + ch * y1.y);
                    // Rz
                    st[i0] = make_float2(ch * z0.x + sh * z0.y, ch * z0.y - sh * z0.x);
                    st[i1] = make_float2(ch * z1.x - sh * z1.y, ch * z1.y + sh * z1.x);
                }
            }
            // CX ring
            const int cs[4] = {0, 1, 2, 3};
            const int ts[4] = {1, 2, 3, 0};
#pragma unroll
            for (int g = 0; g < 4; g++) {
                float2 tmp[16];
                int c = cs[g], t = ts[g];
#pragma unroll
                for (int m = 0; m < 16; m++) tmp[m] = st[m ^ (((m >> c) & 1) << t)];
#pragma unroll
                for (int m = 0; m < 16; m++) st[m] = tmp[m];
            }
        }
#pragma unroll
        for (int x = 0; x < 16; x++) sM[x][tid] = st[x];
    }
    __syncthreads();

    // ---- S table: 544 entries -------------------------------------------
    for (int e = tid; e < 544; e += 256) {
        int pair = e >> 2, q = e & 3;
        int i = 0, rem = pair;
        while (rem >= 16 - i) { rem -= 16 - i; i++; }
        int j = i + rem;
        float s = 0.f;
#pragma unroll
        for (int x = 0; x < 16; x++) {
            float2 mi = sM[x][i], mj = sM[x][j];
            float d = mi.x * mj.x + mi.y * mj.y;
            s += ((x >> q) & 1) ? -d : d;
        }
        sS[pair * 4 + q] = (i == j ? 1.f : 2.f) * s;
    }
    __syncthreads();

    const int r = blockIdx.x * 128 + (tid >> 1);
    const int c = tid & 1;

    // ---- 1) split dot: lane c covers k in [64c, 64c+64), packed f32x2 -----
    const float4* zp = (const float4*)(z + (size_t)r * 128) + c * 16;
    unsigned long long acc01 = 0ull, acc23 = 0ull;
#pragma unroll
    for (int k = 0; k < 16; k++) {
        float4 zv = zp[k];
        int k0 = c * 64 + k * 4;
        ulonglong2 w0 = sWin2[k0], w1 = sWin2[k0 + 1];
        ulonglong2 w2 = sWin2[k0 + 2], w3 = sWin2[k0 + 3];
        unsigned long long zx = pack2(zv.x, zv.x);
        unsigned long long zy = pack2(zv.y, zv.y);
        unsigned long long zz = pack2(zv.z, zv.z);
        unsigned long long zw = pack2(zv.w, zv.w);
        acc01 = ffma2(zx, w0.x, acc01); acc23 = ffma2(zx, w0.y, acc23);
        acc01 = ffma2(zy, w1.x, acc01); acc23 = ffma2(zy, w1.y, acc23);
        acc01 = ffma2(zz, w2.x, acc01); acc23 = ffma2(zz, w2.y, acc23);
        acc01 = ffma2(zw, w3.x, acc01); acc23 = ffma2(zw, w3.y, acc23);
    }
    float ax, ay, az, aw;
    unpack2(acc01, ax, ay);
    unpack2(acc23, az, aw);
    ax += __shfl_xor_sync(0xffffffffu, ax, 1);
    ay += __shfl_xor_sync(0xffffffffu, ay, 1);
    az += __shfl_xor_sync(0xffffffffu, az, 1);
    aw += __shfl_xor_sync(0xffffffffu, aw, 1);

    float a0 = tanhf_fast(ax + sbin[0]);
    float a1 = tanhf_fast(ay + sbin[1]);
    float a2 = tanhf_fast(az + sbin[2]);
    float a3 = tanhf_fast(aw + sbin[3]);

    // ---- 2) s0: real RY product state -------------------------------------
    float c0, s0s, c1, s1s, c2, s2s, c3, s3s;
    __sincosf(0.5f * a0, &s0s, &c0);
    __sincosf(0.5f * a1, &s1s, &c1);
    __sincosf(0.5f * a2, &s2s, &c2);
    __sincosf(0.5f * a3, &s3s, &c3);
    float u0 = c0 * c1, u1 = s0s * c1, u2 = c0 * s1s, u3 = s0s * s1s;
    float v0 = c2 * c3, v1 = s2s * c3, v2 = c2 * s3s, v3 = s2s * s3s;
    float st[16];
    st[0]  = u0 * v0; st[1]  = u1 * v0; st[2]  = u2 * v0; st[3]  = u3 * v0;
    st[4]  = u0 * v1; st[5]  = u1 * v1; st[6]  = u2 * v1; st[7]  = u3 * v1;
    st[8]  = u0 * v2; st[9]  = u1 * v2; st[10] = u2 * v2; st[11] = u3 * v2;
    st[12] = u0 * v3; st[13] = u1 * v3; st[14] = u2 * v3; st[15] = u3 * v3;

    // ---- 3) quadratic forms: lane c computes q = {2c, 2c+1} packed --------
    unsigned long long accA = 0ull, accB = 0ull;   // dual accumulators
    {
        int pidx = 0;
#pragma unroll
        for (int i = 0; i < 16; i++) {
            float si = st[i];
#pragma unroll
            for (int j = i; j < 16; j++) {
                float p = si * st[j];
                unsigned long long pp = pack2(p, p);
                unsigned long long cv =
                    *(const unsigned long long*)&sS[pidx * 4 + 2 * c];  // LDS.64
                if (pidx & 1) accB = ffma2(pp, cv, accB);
                else          accA = ffma2(pp, cv, accA);
                pidx++;
            }
        }
    }
    float xa, ya, xb, yb;
    unpack2(accA, xa, ya);
    unpack2(accB, xb, yb);
    float zqa = xa + xb;     // zq[2c]
    float zqb = ya + yb;     // zq[2c+1]
    float zpa = __shfl_xor_sync(0xffffffffu, zqa, 1);
    float zpb = __shfl_xor_sync(0xffffffffu, zqb, 1);
    float zq0 = c ? zpa : zqa;
    float zq1 = c ? zpb : zqb;
    float zq2 = c ? zqa : zpa;
    float zq3 = c ? zqb : zpb;

    // ---- 4) h = relu(qexp @ W1 + b1), qexp[k]=zq[3-k]; lane c -> m 4c..4c+3
    unsigned long long hh[4];
#pragma unroll
    for (int mm = 0; mm < 4; mm++) {
        int m = 4 * c + mm;
        float t = sb1[m];
        t = fmaf(zq3, sW1[0 * 8 + m], t);
        t = fmaf(zq2, sW1[1 * 8 + m], t);
        t = fmaf(zq1, sW1[2 * 8 + m], t);
        t = fmaf(zq0, sW1[3 * 8 + m], t);
        t = fmaxf(t, 0.f);
        hh[mm] = pack2(t, t);
    }
    ulonglong2* hp = (ulonglong2*)(g_h2 + (size_t)r * 8);
    hp[2 * c + 0] = make_ulonglong2(hh[0], hh[1]);
    hp[2 * c + 1] = make_ulonglong2(hh[2], hh[3]);
}

// ---------------------------------------------------------------------------
// K2: out = sigmoid(h @ W2 + b2). 2 cols/thread; W2 in 8 packed regs.
// ---------------------------------------------------------------------------
#define ROWS_PER_BLOCK 32

__global__ void __launch_bounds__(416, 3) qd_gemm_kernel(
    const float* __restrict__ W2, const float* __restrict__ b2,
    float* __restrict__ out)
{
    __shared__ ulonglong2 sh[ROWS_PER_BLOCK * 4];    // 32 rows x 64B

    int t = threadIdx.x;
    int r0 = blockIdx.x * ROWS_PER_BLOCK;

    if (t < ROWS_PER_BLOCK * 4)
        sh[t] = ((const ulonglong2*)g_h2)[(size_t)r0 * 4 + t];

    unsigned long long w[8];
    unsigned long long bb = 0;
    if (t < 392) {
        const float2* W2v = (const float2*)W2;   // [8][392] float2 view
#pragma unroll
        for (int k = 0; k < 8; k++) {
            float2 wv = W2v[k * 392 + t];
            w[k] = pack2(wv.x, wv.y);
        }
        float2 bv = ((const float2*)b2)[t];
        bb = pack2(bv.x, bv.y);
    }
    __syncthreads();
    if (t >= 392) return;

    float2* outp = (float2*)(out + (size_t)r0 * 784) + t;

#pragma unroll 2
    for (int rr = 0; rr < ROWS_PER_BLOCK; rr++) {
        ulonglong2 h01 = sh[rr * 4 + 0];
        ulonglong2 h23 = sh[rr * 4 + 1];
        ulonglong2 h45 = sh[rr * 4 + 2];
        ulonglong2 h67 = sh[rr * 4 + 3];

        unsigned long long a = bb;
        a = ffma2(h01.x, w[0], a);
        a = ffma2(h01.y, w[1], a);
        a = ffma2(h23.x, w[2], a);
        a = ffma2(h23.y, w[3], a);
        a = ffma2(h45.x, w[4], a);
        a = ffma2(h45.y, w[5], a);
        a = ffma2(h67.x, w[6], a);
        a = ffma2(h67.y, w[7], a);

        float f0, f1;
        unpack2(a, f0, f1);
        outp[(size_t)rr * 392] = make_float2(sigmoidf_fast(f0), sigmoidf_fast(f1));
    }
}

// ---------------------------------------------------------------------------
extern "C" void kernel_launch(void* const* d_in, const int* in_sizes, int n_in,
                              void* d_out, int out_size) {
    const float* z     = (const float*)d_in[0];
    const float* W_in  = (const float*)d_in[1];
    const float* b_in  = (const float*)d_in[2];
    const float* theta = (const float*)d_in[3];
    const float* W1    = (const float*)d_in[4];
    const float* b1    = (const float*)d_in[5];
    const float* W2    = (const float*)d_in[6];
    const float* b2    = (const float*)d_in[7];

    int B = in_sizes[0] / 128;          // 65536
    qd_front_kernel<<<B / 128, 256>>>(z, W_in, b_in, theta, W1, b1);
    qd_gemm_kernel<<<B / ROWS_PER_BLOCK, 416>>>(W2, b2, (float*)d_out);
}

// round 9
// speedup vs baseline: 1.0346x; 1.0346x over previous
#include <cuda_runtime.h>

// ---------------------------------------------------------------------------
// QuantumDecoder: z -> tanh(z@W_in) -> 4-qubit circuit Z-expectations ->
//                 relu(@W1) -> sigmoid(@W2)
//
// Post-RY circuit is a fixed 16x16 unitary M:
//   z_q = s0^T Re(M^H Z_q M) s0 = sum_{i<=j} S_q[i,j] s_i s_j.
//
// R8:
//  K1 (front): R5 structure (1 thread/row, fused per-block sim -> S table),
//     but z staged through smem in 4 coalesced 32-col chunks (padded stride
//     36 words -> conflict-free LDS.128). Fast exp-form tanh.
//  K2 (gemm): R5 structure (4 cols/thread, 224 thr, 16 rows/block, W2 in
//     regs, h staged in smem) + shared-RCP sigmoid: 4 outputs share one
//     MUFU.RCP (5 MUFU per 4 outputs instead of 8).
// ---------------------------------------------------------------------------

__device__ unsigned long long g_h2[65536 * 8];         // h duplicated as f32x2

// ---- packed f32x2 helpers (Blackwell) -------------------------------------
__device__ __forceinline__ unsigned long long pack2(float x, float y) {
    unsigned long long r;
    asm("mov.b64 %0, {%1, %2};" : "=l"(r) : "f"(x), "f"(y));
    return r;
}
__device__ __forceinline__ void unpack2(unsigned long long v, float& x, float& y) {
    asm("mov.b64 {%0, %1}, %2;" : "=f"(x), "=f"(y) : "l"(v));
}
__device__ __forceinline__ unsigned long long ffma2(unsigned long long a,
                                                    unsigned long long b,
                                                    unsigned long long c) {
    unsigned long long d;
    asm("fma.rn.f32x2 %0, %1, %2, %3;" : "=l"(d) : "l"(a), "l"(b), "l"(c));
    return d;
}
__device__ __forceinline__ float tanhf_fast(float x) {
    x = fminf(fmaxf(x, -15.f), 15.f);     // guard exp overflow
    float e = __expf(-2.f * x);
    return __fdividef(1.f - e, 1.f + e);
}

// ---------------------------------------------------------------------------
// K1: front-end. 128 rows/block, 1 thread/row, z staged via smem chunks.
// ---------------------------------------------------------------------------
__global__ void __launch_bounds__(128, 6) qd_front_kernel(
    const float* __restrict__ z,   const float* __restrict__ W_in,
    const float* __restrict__ b_in, const float* __restrict__ theta,
    const float* __restrict__ W1,  const float* __restrict__ b1)
{
    __shared__ float  sZ[128 * 36];     // 32-col chunk, padded stride 36
    __shared__ float4 sWin[128];        // W_in [128][4]
    __shared__ float2 sM[16][16];       // sM[x][j] = <x| fixed-circuit |j>
    __shared__ float4 sS4[136];         // symmetric pair coeffs (4 q's each)
    __shared__ float  sW1[32];          // W1 [4][8]
    __shared__ float  sb1[8];
    __shared__ float  sbin[4];

    int tid = threadIdx.x;
    sWin[tid] = ((const float4*)W_in)[tid];
    if (tid < 32) sW1[tid] = W1[tid];
    if (tid < 8)  sb1[tid] = b1[tid];
    if (tid < 4)  sbin[tid] = b_in[tid];

    // ---- per-block sim of the fixed circuit on basis state |tid> ----------
    if (tid < 16) {
        float2 st[16];
#pragma unroll
        for (int x = 0; x < 16; x++) st[x] = make_float2(0.f, 0.f);
        st[tid] = make_float2(1.f, 0.f);

#pragma unroll
        for (int layer = 0; layer < 2; layer++) {
#pragma unroll
            for (int q = 0; q < 4; q++) {
                float th = theta[layer * 4 + q];
                float ch, sh;
                __sincosf(0.5f * th, &sh, &ch);
                int bit = 1 << q;
#pragma unroll
                for (int a = 0; a < 8; a++) {
                    int i0 = ((a >> q) << (q + 1)) | (a & (bit - 1));
                    int i1 = i0 | bit;
                    float2 x0 = st[i0], x1 = st[i1];
                    // Rx
                    float2 y0 = make_float2(ch * x0.x + sh * x1.y, ch * x0.y - sh * x1.x);
                    float2 y1 = make_float2(ch * x1.x + sh * x0.y, ch * x1.y - sh * x0.x);
                    // Ry
                    float2 z0 = make_float2(ch * y0.x - sh * y1.x, ch * y0.y - sh * y1.y);
                    float2 z1 = make_float2(sh * y0.x + ch * y1.x, sh * y0.y + ch * y1.y);
                    // Rz
                    st[i0] = make_float2(ch * z0.x + sh * z0.y, ch * z0.y - sh * z0.x);
                    st[i1] = make_float2(ch * z1.x - sh * z1.y, ch * z1.y + sh * z1.x);
                }
            }
            const int cs[4] = {0, 1, 2, 3};
            const int ts[4] = {1, 2, 3, 0};
#pragma unroll
            for (int g = 0; g < 4; g++) {
                float2 tmp[16];
                int c = cs[g], t = ts[g];
#pragma unroll
                for (int m = 0; m < 16; m++) tmp[m] = st[m ^ (((m >> c) & 1) << t)];
#pragma unroll
                for (int m = 0; m < 16; m++) st[m] = tmp[m];
            }
        }
#pragma unroll
        for (int x = 0; x < 16; x++) sM[x][tid] = st[x];
    }
    __syncthreads();

    // ---- S table: 544 entries ---------------------------------------------
    for (int e = tid; e < 544; e += 128) {
        int pair = e >> 2, q = e & 3;
        int i = 0, rem = pair;
        while (rem >= 16 - i) { rem -= 16 - i; i++; }
        int j = i + rem;
        float s = 0.f;
#pragma unroll
        for (int x = 0; x < 16; x++) {
            float2 mi = sM[x][i], mj = sM[x][j];
            float d = mi.x * mj.x + mi.y * mj.y;
            s += ((x >> q) & 1) ? -d : d;
        }
        ((float*)sS4)[pair * 4 + q] = (i == j ? 1.f : 2.f) * s;
    }

    const int r0 = blockIdx.x * 128;
    const int r  = r0 + tid;

    // ---- 1) lat = tanh(z_row @ W_in + b_in), z staged via smem ------------
    float ax = sbin[0], ay = sbin[1], az = sbin[2], aw = sbin[3];
    const float4* zg = (const float4*)z;      // [B][32] float4 view

    for (int ch = 0; ch < 4; ch++) {
        __syncthreads();                      // protect previous chunk reads
        // cooperative coalesced load: 1024 float4s (4 rows x 128B per warp-instr)
#pragma unroll
        for (int i = 0; i < 8; i++) {
            int idx = i * 128 + tid;          // 0..1023
            int row = idx >> 3, c4 = idx & 7;
            float4 v = zg[(size_t)(r0 + row) * 32 + ch * 8 + c4];
            *(float4*)&sZ[row * 36 + c4 * 4] = v;
        }
        __syncthreads();
        const float4* zr = (const float4*)&sZ[tid * 36];
#pragma unroll
        for (int k4 = 0; k4 < 8; k4++) {
            float4 zv = zr[k4];
            int k0 = ch * 32 + k4 * 4;
            float4 wa = sWin[k0], wb = sWin[k0 + 1];
            float4 wc = sWin[k0 + 2], wd = sWin[k0 + 3];
            ax = fmaf(zv.x, wa.x, ax); ay = fmaf(zv.x, wa.y, ay);
            az = fmaf(zv.x, wa.z, az); aw = fmaf(zv.x, wa.w, aw);
            ax = fmaf(zv.y, wb.x, ax); ay = fmaf(zv.y, wb.y, ay);
            az = fmaf(zv.y, wb.z, az); aw = fmaf(zv.y, wb.w, aw);
            ax = fmaf(zv.z, wc.x, ax); ay = fmaf(zv.z, wc.y, ay);
            az = fmaf(zv.z, wc.z, az); aw = fmaf(zv.z, wc.w, aw);
            ax = fmaf(zv.w, wd.x, ax); ay = fmaf(zv.w, wd.y, ay);
            az = fmaf(zv.w, wd.z, az); aw = fmaf(zv.w, wd.w, aw);
        }
    }
    float a0 = tanhf_fast(ax), a1 = tanhf_fast(ay);
    float a2 = tanhf_fast(az), a3 = tanhf_fast(aw);

    // ---- 2) s0: real RY product state -------------------------------------
    float c0, s0s, c1, s1s, c2, s2s, c3, s3s;
    __sincosf(0.5f * a0, &s0s, &c0);
    __sincosf(0.5f * a1, &s1s, &c1);
    __sincosf(0.5f * a2, &s2s, &c2);
    __sincosf(0.5f * a3, &s3s, &c3);
    float u0 = c0 * c1, u1 = s0s * c1, u2 = c0 * s1s, u3 = s0s * s1s;
    float v0 = c2 * c3, v1 = s2s * c3, v2 = c2 * s3s, v3 = s2s * s3s;
    float st[16];
    st[0]  = u0 * v0; st[1]  = u1 * v0; st[2]  = u2 * v0; st[3]  = u3 * v0;
    st[4]  = u0 * v1; st[5]  = u1 * v1; st[6]  = u2 * v1; st[7]  = u3 * v1;
    st[8]  = u0 * v2; st[9]  = u1 * v2; st[10] = u2 * v2; st[11] = u3 * v2;
    st[12] = u0 * v3; st[13] = u1 * v3; st[14] = u2 * v3; st[15] = u3 * v3;

    // ---- 3) all 4 quadratic forms via symmetric pair table ----------------
    float zq0 = 0.f, zq1 = 0.f, zq2 = 0.f, zq3 = 0.f;
    {
        int pidx = 0;
#pragma unroll
        for (int i = 0; i < 16; i++) {
            float si = st[i];
#pragma unroll
            for (int j = i; j < 16; j++) {
                float p = si * st[j];
                float4 cv = sS4[pidx++];
                zq0 = fmaf(p, cv.x, zq0);
                zq1 = fmaf(p, cv.y, zq1);
                zq2 = fmaf(p, cv.z, zq2);
                zq3 = fmaf(p, cv.w, zq3);
            }
        }
    }

    // ---- 4) h = relu(qexp @ W1 + b1);  qexp[k] = zq[3-k]; store dup'd -----
    unsigned long long hh[8];
#pragma unroll
    for (int m = 0; m < 8; m++) {
        float t = sb1[m];
        t = fmaf(zq3, sW1[0 * 8 + m], t);
        t = fmaf(zq2, sW1[1 * 8 + m], t);
        t = fmaf(zq1, sW1[2 * 8 + m], t);
        t = fmaf(zq0, sW1[3 * 8 + m], t);
        t = fmaxf(t, 0.f);
        hh[m] = pack2(t, t);
    }
    ulonglong2* hp = (ulonglong2*)(g_h2 + (size_t)r * 8);
    hp[0] = make_ulonglong2(hh[0], hh[1]);
    hp[1] = make_ulonglong2(hh[2], hh[3]);
    hp[2] = make_ulonglong2(hh[4], hh[5]);
    hp[3] = make_ulonglong2(hh[6], hh[7]);
}

// ---------------------------------------------------------------------------
// K2: out = sigmoid(h @ W2 + b2). 4 cols/thread, W2 in regs, shared-RCP
// sigmoid (4 EX2 + 1 RCP per 4 outputs).
// ---------------------------------------------------------------------------
#define ROWS_PER_BLOCK 16

__global__ void __launch_bounds__(224, 4) qd_gemm_kernel(
    const float* __restrict__ W2, const float* __restrict__ b2,
    float* __restrict__ out)
{
    __shared__ ulonglong2 sh[ROWS_PER_BLOCK * 4];    // 16 rows x 64B

    int t = threadIdx.x;
    int r0 = blockIdx.x * ROWS_PER_BLOCK;

    if (t < ROWS_PER_BLOCK * 4)
        sh[t] = ((const ulonglong2*)g_h2)[(size_t)r0 * 4 + t];

    unsigned long long w[8][2];
    unsigned long long bb0 = 0, bb1 = 0;
    if (t < 196) {
        const float4* W2v = (const float4*)W2;   // [8][196] float4 view
#pragma unroll
        for (int k = 0; k < 8; k++) {
            float4 wv = W2v[k * 196 + t];
            w[k][0] = pack2(wv.x, wv.y);
            w[k][1] = pack2(wv.z, wv.w);
        }
        float4 bv = ((const float4*)b2)[t];
        bb0 = pack2(bv.x, bv.y);
        bb1 = pack2(bv.z, bv.w);
    }
    __syncthreads();
    if (t >= 196) return;

    float* outp = out + (size_t)r0 * 784 + 4 * t;

#pragma unroll 4
    for (int rr = 0; rr < ROWS_PER_BLOCK; rr++) {
        ulonglong2 h01 = sh[rr * 4 + 0];
        ulonglong2 h23 = sh[rr * 4 + 1];
        ulonglong2 h45 = sh[rr * 4 + 2];
        ulonglong2 h67 = sh[rr * 4 + 3];

        unsigned long long a0 = bb0, a1 = bb1;
        a0 = ffma2(h01.x, w[0][0], a0);  a1 = ffma2(h01.x, w[0][1], a1);
        a0 = ffma2(h01.y, w[1][0], a0);  a1 = ffma2(h01.y, w[1][1], a1);
        a0 = ffma2(h23.x, w[2][0], a0);  a1 = ffma2(h23.x, w[2][1], a1);
        a0 = ffma2(h23.y, w[3][0], a0);  a1 = ffma2(h23.y, w[3][1], a1);
        a0 = ffma2(h45.x, w[4][0], a0);  a1 = ffma2(h45.x, w[4][1], a1);
        a0 = ffma2(h45.y, w[5][0], a0);  a1 = ffma2(h45.y, w[5][1], a1);
        a0 = ffma2(h67.x, w[6][0], a0);  a1 = ffma2(h67.x, w[6][1], a1);
        a0 = ffma2(h67.y, w[7][0], a0);  a1 = ffma2(h67.y, w[7][1], a1);

        float f0, f1, f2, f3;
        unpack2(a0, f0, f1);
        unpack2(a1, f2, f3);

        // shared-RCP sigmoid: s_i = (prod_{j!=i} d_j) / (prod_j d_j)
        float e0 = __expf(-fmaxf(f0, -20.f));
        float e1 = __expf(-fmaxf(f1, -20.f));
        float e2 = __expf(-fmaxf(f2, -20.f));
        float e3 = __expf(-fmaxf(f3, -20.f));
        float d0 = 1.f + e0, d1 = 1.f + e1, d2 = 1.f + e2, d3 = 1.f + e3;
        float P01 = d0 * d1, P23 = d2 * d3;
        float rinv = __fdividef(1.f, P01 * P23);   // one MUFU.RCP
        float q01 = rinv * P23, q23 = rinv * P01;
        *(float4*)(outp + (size_t)rr * 784) =
            make_float4(q01 * d1, q01 * d0, q23 * d3, q23 * d2);
    }
}

// ---------------------------------------------------------------------------
extern "C" void kernel_launch(void* const* d_in, const int* in_sizes, int n_in,
                              void* d_out, int out_size) {
    const float* z     = (const float*)d_in[0];
    const float* W_in  = (const float*)d_in[1];
    const float* b_in  = (const float*)d_in[2];
    const float* theta = (const float*)d_in[3];
    const float* W1    = (const float*)d_in[4];
    const float* b1    = (const float*)d_in[5];
    const float* W2    = (const float*)d_in[6];
    const float* b2    = (const float*)d_in[7];

    int B = in_sizes[0] / 128;          // 65536
    qd_front_kernel<<<B / 128, 128>>>(z, W_in, b_in, theta, W1, b1);
    qd_gemm_kernel<<<B / ROWS_PER_BLOCK, 224>>>(W2, b2, (float*)d_out);
}

// round 10
// speedup vs baseline: 1.1036x; 1.0667x over previous
#include <cuda_runtime.h>

// ---------------------------------------------------------------------------
// QuantumDecoder: z -> tanh(z@W_in) -> 4-qubit circuit Z-expectations ->
//                 relu(@W1) -> sigmoid(@W2)
//
// Post-RY circuit is a fixed 16x16 unitary M:
//   z_q = s0^T Re(M^H Z_q M) s0 = sum_{i<=j} S_q[i,j] s_i s_j.
//
// R10:
//  K1 (front): 1 thread/row, fused per-block sim -> S table; z staged via
//     smem in 2 coalesced 64-col chunks (stride 68 words, conflict-free).
//  K2 (gemm): R5-proven form: 4 cols/thread, 224 thr, 16 rows/block, W2 in
//     regs, h staged in smem, per-element exp+rcp sigmoid (best ILP).
// ---------------------------------------------------------------------------

__device__ unsigned long long g_h2[65536 * 8];         // h duplicated as f32x2

// ---- packed f32x2 helpers (Blackwell) -------------------------------------
__device__ __forceinline__ unsigned long long pack2(float x, float y) {
    unsigned long long r;
    asm("mov.b64 %0, {%1, %2};" : "=l"(r) : "f"(x), "f"(y));
    return r;
}
__device__ __forceinline__ void unpack2(unsigned long long v, float& x, float& y) {
    asm("mov.b64 {%0, %1}, %2;" : "=f"(x), "=f"(y) : "l"(v));
}
__device__ __forceinline__ unsigned long long ffma2(unsigned long long a,
                                                    unsigned long long b,
                                                    unsigned long long c) {
    unsigned long long d;
    asm("fma.rn.f32x2 %0, %1, %2, %3;" : "=l"(d) : "l"(a), "l"(b), "l"(c));
    return d;
}
__device__ __forceinline__ float sigmoidf_fast(float x) {
    float e = __expf(-x);                 // MUFU.EX2 path
    return __fdividef(1.0f, 1.0f + e);    // MUFU.RCP path
}
__device__ __forceinline__ float tanhf_fast(float x) {
    x = fminf(fmaxf(x, -15.f), 15.f);     // guard exp overflow
    float e = __expf(-2.f * x);
    return __fdividef(1.f - e, 1.f + e);
}

// ---------------------------------------------------------------------------
// K1: front-end. 128 rows/block, 1 thread/row, z staged via 64-col chunks.
// ---------------------------------------------------------------------------
#define ZSTRIDE 68   // words; 17x16B (odd) -> conflict-free LDS.128/STS.128

__global__ void __launch_bounds__(128, 5) qd_front_kernel(
    const float* __restrict__ z,   const float* __restrict__ W_in,
    const float* __restrict__ b_in, const float* __restrict__ theta,
    const float* __restrict__ W1,  const float* __restrict__ b1)
{
    __shared__ float  sZ[128 * ZSTRIDE];  // 64-col chunk, padded stride
    __shared__ float4 sWin[128];          // W_in [128][4]
    __shared__ float2 sM[16][16];         // sM[x][j] = <x| fixed-circuit |j>
    __shared__ float4 sS4[136];           // symmetric pair coeffs (4 q's)
    __shared__ float  sW1[32];            // W1 [4][8]
    __shared__ float  sb1[8];
    __shared__ float  sbin[4];

    int tid = threadIdx.x;
    sWin[tid] = ((const float4*)W_in)[tid];
    if (tid < 32) sW1[tid] = W1[tid];
    if (tid < 8)  sb1[tid] = b1[tid];
    if (tid < 4)  sbin[tid] = b_in[tid];

    // ---- per-block sim of the fixed circuit on basis state |tid> ----------
    if (tid < 16) {
        float2 st[16];
#pragma unroll
        for (int x = 0; x < 16; x++) st[x] = make_float2(0.f, 0.f);
        st[tid] = make_float2(1.f, 0.f);

#pragma unroll
        for (int layer = 0; layer < 2; layer++) {
#pragma unroll
            for (int q = 0; q < 4; q++) {
                float th = theta[layer * 4 + q];
                float ch, sh;
                __sincosf(0.5f * th, &sh, &ch);
                int bit = 1 << q;
#pragma unroll
                for (int a = 0; a < 8; a++) {
                    int i0 = ((a >> q) << (q + 1)) | (a & (bit - 1));
                    int i1 = i0 | bit;
                    float2 x0 = st[i0], x1 = st[i1];
                    // Rx
                    float2 y0 = make_float2(ch * x0.x + sh * x1.y, ch * x0.y - sh * x1.x);
                    float2 y1 = make_float2(ch * x1.x + sh * x0.y, ch * x1.y - sh * x0.x);
                    // Ry
                    float2 z0 = make_float2(ch * y0.x - sh * y1.x, ch * y0.y - sh * y1.y);
                    float2 z1 = make_float2(sh * y0.x + ch * y1.x, sh * y0.y + ch * y1.y);
                    // Rz
                    st[i0] = make_float2(ch * z0.x + sh * z0.y, ch * z0.y - sh * z0.x);
                    st[i1] = make_float2(ch * z1.x - sh * z1.y, ch * z1.y + sh * z1.x);
                }
            }
            const int cs[4] = {0, 1, 2, 3};
            const int ts[4] = {1, 2, 3, 0};
#pragma unroll
            for (int g = 0; g < 4; g++) {
                float2 tmp[16];
                int c = cs[g], t = ts[g];
#pragma unroll
                for (int m = 0; m < 16; m++) tmp[m] = st[m ^ (((m >> c) & 1) << t)];
#pragma unroll
                for (int m = 0; m < 16; m++) st[m] = tmp[m];
            }
        }
#pragma unroll
        for (int x = 0; x < 16; x++) sM[x][tid] = st[x];
    }
    __syncthreads();

    // ---- S table: 544 entries ---------------------------------------------
    for (int e = tid; e < 544; e += 128) {
        int pair = e >> 2, q = e & 3;
        int i = 0, rem = pair;
        while (rem >= 16 - i) { rem -= 16 - i; i++; }
        int j = i + rem;
        float s = 0.f;
#pragma unroll
        for (int x = 0; x < 16; x++) {
            float2 mi = sM[x][i], mj = sM[x][j];
            float d = mi.x * mj.x + mi.y * mj.y;
            s += ((x >> q) & 1) ? -d : d;
        }
        ((float*)sS4)[pair * 4 + q] = (i == j ? 1.f : 2.f) * s;
    }

    const int r0 = blockIdx.x * 128;
    const int r  = r0 + tid;

    // ---- 1) lat = tanh(z_row @ W_in + b_in), z via 2 smem chunks ----------
    float ax = sbin[0], ay = sbin[1], az = sbin[2], aw = sbin[3];
    const float4* zg = (const float4*)z;      // [B][32] float4 view

#pragma unroll
    for (int ch = 0; ch < 2; ch++) {
        __syncthreads();                      // protect previous chunk reads
        // cooperative coalesced load: 2048 float4s, 16 per thread (deep MLP)
#pragma unroll
        for (int i = 0; i < 16; i++) {
            int idx = i * 128 + tid;          // 0..2047
            int row = idx >> 4, c4 = idx & 15;
            float4 v = zg[(size_t)(r0 + row) * 32 + ch * 16 + c4];
            *(float4*)&sZ[row * ZSTRIDE + c4 * 4] = v;
        }
        __syncthreads();
        const float4* zr = (const float4*)&sZ[tid * ZSTRIDE];
#pragma unroll
        for (int k4 = 0; k4 < 16; k4++) {
            float4 zv = zr[k4];
            int k0 = ch * 64 + k4 * 4;
            float4 wa = sWin[k0], wb = sWin[k0 + 1];
            float4 wc = sWin[k0 + 2], wd = sWin[k0 + 3];
            ax = fmaf(zv.x, wa.x, ax); ay = fmaf(zv.x, wa.y, ay);
            az = fmaf(zv.x, wa.z, az); aw = fmaf(zv.x, wa.w, aw);
            ax = fmaf(zv.y, wb.x, ax); ay = fmaf(zv.y, wb.y, ay);
            az = fmaf(zv.y, wb.z, az); aw = fmaf(zv.y, wb.w, aw);
            ax = fmaf(zv.z, wc.x, ax); ay = fmaf(zv.z, wc.y, ay);
            az = fmaf(zv.z, wc.z, az); aw = fmaf(zv.z, wc.w, aw);
            ax = fmaf(zv.w, wd.x, ax); ay = fmaf(zv.w, wd.y, ay);
            az = fmaf(zv.w, wd.z, az); aw = fmaf(zv.w, wd.w, aw);
        }
    }
    float a0 = tanhf_fast(ax), a1 = tanhf_fast(ay);
    float a2 = tanhf_fast(az), a3 = tanhf_fast(aw);

    // ---- 2) s0: real RY product state -------------------------------------
    float c0, s0s, c1, s1s, c2, s2s, c3, s3s;
    __sincosf(0.5f * a0, &s0s, &c0);
    __sincosf(0.5f * a1, &s1s, &c1);
    __sincosf(0.5f * a2, &s2s, &c2);
    __sincosf(0.5f * a3, &s3s, &c3);
    float u0 = c0 * c1, u1 = s0s * c1, u2 = c0 * s1s, u3 = s0s * s1s;
    float v0 = c2 * c3, v1 = s2s * c3, v2 = c2 * s3s, v3 = s2s * s3s;
    float st[16];
    st[0]  = u0 * v0; st[1]  = u1 * v0; st[2]  = u2 * v0; st[3]  = u3 * v0;
    st[4]  = u0 * v1; st[5]  = u1 * v1; st[6]  = u2 * v1; st[7]  = u3 * v1;
    st[8]  = u0 * v2; st[9]  = u1 * v2; st[10] = u2 * v2; st[11] = u3 * v2;
    st[12] = u0 * v3; st[13] = u1 * v3; st[14] = u2 * v3; st[15] = u3 * v3;

    // ---- 3) all 4 quadratic forms via symmetric pair table ----------------
    float zq0 = 0.f, zq1 = 0.f, zq2 = 0.f, zq3 = 0.f;
    {
        int pidx = 0;
#pragma unroll
        for (int i = 0; i < 16; i++) {
            float si = st[i];
#pragma unroll
            for (int j = i; j < 16; j++) {
                float p = si * st[j];
                float4 cv = sS4[pidx++];
                zq0 = fmaf(p, cv.x, zq0);
                zq1 = fmaf(p, cv.y, zq1);
                zq2 = fmaf(p, cv.z, zq2);
                zq3 = fmaf(p, cv.w, zq3);
            }
        }
    }

    // ---- 4) h = relu(qexp @ W1 + b1);  qexp[k] = zq[3-k]; store dup'd -----
    unsigned long long hh[8];
#pragma unroll
    for (int m = 0; m < 8; m++) {
        float t = sb1[m];
        t = fmaf(zq3, sW1[0 * 8 + m], t);
        t = fmaf(zq2, sW1[1 * 8 + m], t);
        t = fmaf(zq1, sW1[2 * 8 + m], t);
        t = fmaf(zq0, sW1[3 * 8 + m], t);
        t = fmaxf(t, 0.f);
        hh[m] = pack2(t, t);
    }
    ulonglong2* hp = (ulonglong2*)(g_h2 + (size_t)r * 8);
    hp[0] = make_ulonglong2(hh[0], hh[1]);
    hp[1] = make_ulonglong2(hh[2], hh[3]);
    hp[2] = make_ulonglong2(hh[4], hh[5]);
    hp[3] = make_ulonglong2(hh[6], hh[7]);
}

// ---------------------------------------------------------------------------
// K2: out = sigmoid(h @ W2 + b2). R5-proven: 4 cols/thread, W2 in regs,
// h staged in smem, per-element exp+rcp sigmoid.
// ---------------------------------------------------------------------------
#define ROWS_PER_BLOCK 16

__global__ void __launch_bounds__(224, 4) qd_gemm_kernel(
    const float* __restrict__ W2, const float* __restrict__ b2,
    float* __restrict__ out)
{
    __shared__ ulonglong2 sh[ROWS_PER_BLOCK * 4];    // 16 rows x 64B

    int t = threadIdx.x;
    int r0 = blockIdx.x * ROWS_PER_BLOCK;

    if (t < ROWS_PER_BLOCK * 4)
        sh[t] = ((const ulonglong2*)g_h2)[(size_t)r0 * 4 + t];

    unsigned long long w[8][2];
    unsigned long long bb0 = 0, bb1 = 0;
    if (t < 196) {
        const float4* W2v = (const float4*)W2;   // [8][196] float4 view
#pragma unroll
        for (int k = 0; k < 8; k++) {
            float4 wv = W2v[k * 196 + t];
            w[k][0] = pack2(wv.x, wv.y);
            w[k][1] = pack2(wv.z, wv.w);
        }
        float4 bv = ((const float4*)b2)[t];
        bb0 = pack2(bv.x, bv.y);
        bb1 = pack2(bv.z, bv.w);
    }
    __syncthreads();
    if (t >= 196) return;

    float* outp = out + (size_t)r0 * 784 + 4 * t;

#pragma unroll 4
    for (int rr = 0; rr < ROWS_PER_BLOCK; rr++) {
        ulonglong2 h01 = sh[rr * 4 + 0];
        ulonglong2 h23 = sh[rr * 4 + 1];
        ulonglong2 h45 = sh[rr * 4 + 2];
        ulonglong2 h67 = sh[rr * 4 + 3];

        unsigned long long a0 = bb0, a1 = bb1;
        a0 = ffma2(h01.x, w[0][0], a0);  a1 = ffma2(h01.x, w[0][1], a1);
        a0 = ffma2(h01.y, w[1][0], a0);  a1 = ffma2(h01.y, w[1][1], a1);
        a0 = ffma2(h23.x, w[2][0], a0);  a1 = ffma2(h23.x, w[2][1], a1);
        a0 = ffma2(h23.y, w[3][0], a0);  a1 = ffma2(h23.y, w[3][1], a1);
        a0 = ffma2(h45.x, w[4][0], a0);  a1 = ffma2(h45.x, w[4][1], a1);
        a0 = ffma2(h45.y, w[5][0], a0);  a1 = ffma2(h45.y, w[5][1], a1);
        a0 = ffma2(h67.x, w[6][0], a0);  a1 = ffma2(h67.x, w[6][1], a1);
        a0 = ffma2(h67.y, w[7][0], a0);  a1 = ffma2(h67.y, w[7][1], a1);

        float f0, f1, f2, f3;
        unpack2(a0, f0, f1);
        unpack2(a1, f2, f3);
        *(float4*)(outp + (size_t)rr * 784) =
            make_float4(sigmoidf_fast(f0), sigmoidf_fast(f1),
                        sigmoidf_fast(f2), sigmoidf_fast(f3));
    }
}

// ---------------------------------------------------------------------------
extern "C" void kernel_launch(void* const* d_in, const int* in_sizes, int n_in,
                              void* d_out, int out_size) {
    const float* z     = (const float*)d_in[0];
    const float* W_in  = (const float*)d_in[1];
    const float* b_in  = (const float*)d_in[2];
    const float* theta = (const float*)d_in[3];
    const float* W1    = (const float*)d_in[4];
    const float* b1    = (const float*)d_in[5];
    const float* W2    = (const float*)d_in[6];
    const float* b2    = (const float*)d_in[7];

    int B = in_sizes[0] / 128;          // 65536
    qd_front_kernel<<<B / 128, 128>>>(z, W_in, b_in, theta, W1, b1);
    qd_gemm_kernel<<<B / ROWS_PER_BLOCK, 224>>>(W2, b2, (float*)d_out);
}

// round 11
// speedup vs baseline: 1.2395x; 1.1231x over previous
#include <cuda_runtime.h>

// ---------------------------------------------------------------------------
// QuantumDecoder: z -> tanh(z@W_in) -> 4-qubit circuit Z-expectations ->
//                 relu(@W1) -> sigmoid(@W2)
//
// Post-RY circuit is a fixed 16x16 unitary M:
//   z_q = s0^T Re(M^H Z_q M) s0 = sum_{i<=j} S_q[i,j] s_i s_j.
//
// R11:
//  K1 (front): 1 thread/row, fused per-block sim -> S table. z staged via
//     smem in 4x32-col chunks, DOUBLE-BUFFERED + register-prefetched:
//     chunk0's DRAM latency hides under the sim; later chunks hide under
//     the previous chunk's FMAs. launch_bounds(128,4) to avoid spills.
//  K2 (gemm): R5/R10-proven: 4 cols/thread, 224 thr, 16 rows/block, W2 in
//     regs, h staged in smem, per-element exp+rcp sigmoid; __stcs stores.
// ---------------------------------------------------------------------------

__device__ unsigned long long g_h2[65536 * 8];         // h duplicated as f32x2

// ---- packed f32x2 helpers (Blackwell) -------------------------------------
__device__ __forceinline__ unsigned long long pack2(float x, float y) {
    unsigned long long r;
    asm("mov.b64 %0, {%1, %2};" : "=l"(r) : "f"(x), "f"(y));
    return r;
}
__device__ __forceinline__ void unpack2(unsigned long long v, float& x, float& y) {
    asm("mov.b64 {%0, %1}, %2;" : "=f"(x), "=f"(y) : "l"(v));
}
__device__ __forceinline__ unsigned long long ffma2(unsigned long long a,
                                                    unsigned long long b,
                                                    unsigned long long c) {
    unsigned long long d;
    asm("fma.rn.f32x2 %0, %1, %2, %3;" : "=l"(d) : "l"(a), "l"(b), "l"(c));
    return d;
}
__device__ __forceinline__ float sigmoidf_fast(float x) {
    float e = __expf(-x);                 // MUFU.EX2
    return __fdividef(1.0f, 1.0f + e);    // MUFU.RCP
}
__device__ __forceinline__ float tanhf_fast(float x) {
    x = fminf(fmaxf(x, -15.f), 15.f);     // guard exp overflow
    float e = __expf(-2.f * x);
    return __fdividef(1.f - e, 1.f + e);
}

// ---------------------------------------------------------------------------
// K1: front-end. 128 rows/block, 1 thread/row; pipelined 32-col z chunks.
// ---------------------------------------------------------------------------
#define ZS 36   // words per row per chunk buffer (9x16B, odd -> conflict-free LDS.128)

__global__ void __launch_bounds__(128, 4) qd_front_kernel(
    const float* __restrict__ z,   const float* __restrict__ W_in,
    const float* __restrict__ b_in, const float* __restrict__ theta,
    const float* __restrict__ W1,  const float* __restrict__ b1)
{
    __shared__ float  sZ[2][128 * ZS];    // double-buffered 32-col chunk
    __shared__ float4 sWin[128];          // W_in [128][4]
    __shared__ float2 sM[16][16];         // sM[x][j] = <x| fixed-circuit |j>
    __shared__ float4 sS4[136];           // symmetric pair coeffs (4 q's)
    __shared__ float  sW1[32];            // W1 [4][8]
    __shared__ float  sb1[8];
    __shared__ float  sbin[4];

    const int tid = threadIdx.x;
    const int r0  = blockIdx.x * 128;
    const int r   = r0 + tid;
    const float4* zg = (const float4*)z;  // [B][32] float4 view

    sWin[tid] = ((const float4*)W_in)[tid];
    if (tid < 32) sW1[tid] = W1[tid];
    if (tid < 8)  sb1[tid] = b1[tid];
    if (tid < 4)  sbin[tid] = b_in[tid];

    const int prow = tid >> 3;            // cooperative-load row step base
    const int pc4  = tid & 7;             // float4 index within 32-col chunk

    // ---- prefetch chunk 0 into registers (hides under the sim) ------------
    float4 pf[8];
#pragma unroll
    for (int i = 0; i < 8; i++)
        pf[i] = zg[(size_t)(r0 + i * 16 + prow) * 32 + 0 * 8 + pc4];

    // ---- per-block sim of the fixed circuit on basis state |tid> ----------
    if (tid < 16) {
        float2 st[16];
#pragma unroll
        for (int x = 0; x < 16; x++) st[x] = make_float2(0.f, 0.f);
        st[tid] = make_float2(1.f, 0.f);

#pragma unroll
        for (int layer = 0; layer < 2; layer++) {
#pragma unroll
            for (int q = 0; q < 4; q++) {
                float th = theta[layer * 4 + q];
                float ch, sh;
                __sincosf(0.5f * th, &sh, &ch);
                int bit = 1 << q;
#pragma unroll
                for (int a = 0; a < 8; a++) {
                    int i0 = ((a >> q) << (q + 1)) | (a & (bit - 1));
                    int i1 = i0 | bit;
                    float2 x0 = st[i0], x1 = st[i1];
                    // Rx
                    float2 y0 = make_float2(ch * x0.x + sh * x1.y, ch * x0.y - sh * x1.x);
                    float2 y1 = make_float2(ch * x1.x + sh * x0.y, ch * x1.y - sh * x0.x);
                    // Ry
                    float2 z0 = make_float2(ch * y0.x - sh * y1.x, ch * y0.y - sh * y1.y);
                    float2 z1 = make_float2(sh * y0.x + ch * y1.x, sh * y0.y + ch * y1.y);
                    // Rz
                    st[i0] = make_float2(ch * z0.x + sh * z0.y, ch * z0.y - sh * z0.x);
                    st[i1] = make_float2(ch * z1.x - sh * z1.y, ch * z1.y + sh * z1.x);
                }
            }
            const int cs[4] = {0, 1, 2, 3};
            const int ts[4] = {1, 2, 3, 0};
#pragma unroll
            for (int g = 0; g < 4; g++) {
                float2 tmp[16];
                int c = cs[g], t = ts[g];
#pragma unroll
                for (int m = 0; m < 16; m++) tmp[m] = st[m ^ (((m >> c) & 1) << t)];
#pragma unroll
                for (int m = 0; m < 16; m++) st[m] = tmp[m];
            }
        }
#pragma unroll
        for (int x = 0; x < 16; x++) sM[x][tid] = st[x];
    }
    __syncthreads();                      // sM ready

    // ---- S table: 544 entries ---------------------------------------------
    for (int e = tid; e < 544; e += 128) {
        int pair = e >> 2, q = e & 3;
        int i = 0, rem = pair;
        while (rem >= 16 - i) { rem -= 16 - i; i++; }
        int j = i + rem;
        float s = 0.f;
#pragma unroll
        for (int x = 0; x < 16; x++) {
            float2 mi = sM[x][i], mj = sM[x][j];
            float d = mi.x * mj.x + mi.y * mj.y;
            s += ((x >> q) & 1) ? -d : d;
        }
        ((float*)sS4)[pair * 4 + q] = (i == j ? 1.f : 2.f) * s;
    }

    // ---- commit chunk 0, prefetch chunk 1 ---------------------------------
#pragma unroll
    for (int i = 0; i < 8; i++)
        *(float4*)&sZ[0][(i * 16 + prow) * ZS + pc4 * 4] = pf[i];
#pragma unroll
    for (int i = 0; i < 8; i++)
        pf[i] = zg[(size_t)(r0 + i * 16 + prow) * 32 + 1 * 8 + pc4];
    __syncthreads();                      // sZ[0] + sS4 ready

    // ---- 1) lat = tanh(z_row @ W_in + b_in), pipelined chunks -------------
    float ax = sbin[0], ay = sbin[1], az = sbin[2], aw = sbin[3];

#pragma unroll
    for (int ch = 0; ch < 4; ch++) {
        if (ch < 3) {
            // commit prefetched chunk ch+1 into the other buffer
#pragma unroll
            for (int i = 0; i < 8; i++)
                *(float4*)&sZ[(ch + 1) & 1][(i * 16 + prow) * ZS + pc4 * 4] = pf[i];
            if (ch < 2) {
                // issue LDG for chunk ch+2 (consumed after next barrier)
#pragma unroll
                for (int i = 0; i < 8; i++)
                    pf[i] = zg[(size_t)(r0 + i * 16 + prow) * 32 + (ch + 2) * 8 + pc4];
            }
        }
        const float4* zr = (const float4*)&sZ[ch & 1][tid * ZS];
#pragma unroll
        for (int k4 = 0; k4 < 8; k4++) {
            float4 zv = zr[k4];
            int k0 = ch * 32 + k4 * 4;
            float4 wa = sWin[k0], wb = sWin[k0 + 1];
            float4 wc = sWin[k0 + 2], wd = sWin[k0 + 3];
            ax = fmaf(zv.x, wa.x, ax); ay = fmaf(zv.x, wa.y, ay);
            az = fmaf(zv.x, wa.z, az); aw = fmaf(zv.x, wa.w, aw);
            ax = fmaf(zv.y, wb.x, ax); ay = fmaf(zv.y, wb.y, ay);
            az = fmaf(zv.y, wb.z, az); aw = fmaf(zv.y, wb.w, aw);
            ax = fmaf(zv.z, wc.x, ax); ay = fmaf(zv.z, wc.y, ay);
            az = fmaf(zv.z, wc.z, az); aw = fmaf(zv.z, wc.w, aw);
            ax = fmaf(zv.w, wd.x, ax); ay = fmaf(zv.w, wd.y, ay);
            az = fmaf(zv.w, wd.z, az); aw = fmaf(zv.w, wd.w, aw);
        }
        if (ch < 3) __syncthreads();
    }
    float a0 = tanhf_fast(ax), a1 = tanhf_fast(ay);
    float a2 = tanhf_fast(az), a3 = tanhf_fast(aw);

    // ---- 2) s0: real RY product state -------------------------------------
    float c0, s0s, c1, s1s, c2, s2s, c3, s3s;
    __sincosf(0.5f * a0, &s0s, &c0);
    __sincosf(0.5f * a1, &s1s, &c1);
    __sincosf(0.5f * a2, &s2s, &c2);
    __sincosf(0.5f * a3, &s3s, &c3);
    float u0 = c0 * c1, u1 = s0s * c1, u2 = c0 * s1s, u3 = s0s * s1s;
    float v0 = c2 * c3, v1 = s2s * c3, v2 = c2 * s3s, v3 = s2s * s3s;
    float st[16];
    st[0]  = u0 * v0; st[1]  = u1 * v0; st[2]  = u2 * v0; st[3]  = u3 * v0;
    st[4]  = u0 * v1; st[5]  = u1 * v1; st[6]  = u2 * v1; st[7]  = u3 * v1;
    st[8]  = u0 * v2; st[9]  = u1 * v2; st[10] = u2 * v2; st[11] = u3 * v2;
    st[12] = u0 * v3; st[13] = u1 * v3; st[14] = u2 * v3; st[15] = u3 * v3;

    // ---- 3) all 4 quadratic forms via symmetric pair table ----------------
    float zq0 = 0.f, zq1 = 0.f, zq2 = 0.f, zq3 = 0.f;
    {
        int pidx = 0;
#pragma unroll
        for (int i = 0; i < 16; i++) {
            float si = st[i];
#pragma unroll
            for (int j = i; j < 16; j++) {
                float p = si * st[j];
                float4 cv = sS4[pidx++];
                zq0 = fmaf(p, cv.x, zq0);
                zq1 = fmaf(p, cv.y, zq1);
                zq2 = fmaf(p, cv.z, zq2);
                zq3 = fmaf(p, cv.w, zq3);
            }
        }
    }

    // ---- 4) h = relu(qexp @ W1 + b1);  qexp[k] = zq[3-k]; store dup'd -----
    unsigned long long hh[8];
#pragma unroll
    for (int m = 0; m < 8; m++) {
        float t = sb1[m];
        t = fmaf(zq3, sW1[0 * 8 + m], t);
        t = fmaf(zq2, sW1[1 * 8 + m], t);
        t = fmaf(zq1, sW1[2 * 8 + m], t);
        t = fmaf(zq0, sW1[3 * 8 + m], t);
        t = fmaxf(t, 0.f);
        hh[m] = pack2(t, t);
    }
    ulonglong2* hp = (ulonglong2*)(g_h2 + (size_t)r * 8);
    hp[0] = make_ulonglong2(hh[0], hh[1]);
    hp[1] = make_ulonglong2(hh[2], hh[3]);
    hp[2] = make_ulonglong2(hh[4], hh[5]);
    hp[3] = make_ulonglong2(hh[6], hh[7]);
}

// ---------------------------------------------------------------------------
// K2: out = sigmoid(h @ W2 + b2). 4 cols/thread, W2 in regs, h staged in
// smem, per-element exp+rcp sigmoid, evict-first stores.
// ---------------------------------------------------------------------------
#define ROWS_PER_BLOCK 16

__global__ void __launch_bounds__(224, 4) qd_gemm_kernel(
    const float* __restrict__ W2, const float* __restrict__ b2,
    float* __restrict__ out)
{
    __shared__ ulonglong2 sh[ROWS_PER_BLOCK * 4];    // 16 rows x 64B

    int t = threadIdx.x;
    int r0 = blockIdx.x * ROWS_PER_BLOCK;

    if (t < ROWS_PER_BLOCK * 4)
        sh[t] = ((const ulonglong2*)g_h2)[(size_t)r0 * 4 + t];

    unsigned long long w[8][2];
    unsigned long long bb0 = 0, bb1 = 0;
    if (t < 196) {
        const float4* W2v = (const float4*)W2;   // [8][196] float4 view
#pragma unroll
        for (int k = 0; k < 8; k++) {
            float4 wv = W2v[k * 196 + t];
            w[k][0] = pack2(wv.x, wv.y);
            w[k][1] = pack2(wv.z, wv.w);
        }
        float4 bv = ((const float4*)b2)[t];
        bb0 = pack2(bv.x, bv.y);
        bb1 = pack2(bv.z, bv.w);
    }
    __syncthreads();
    if (t >= 196) return;

    float* outp = out + (size_t)r0 * 784 + 4 * t;

#pragma unroll 4
    for (int rr = 0; rr < ROWS_PER_BLOCK; rr++) {
        ulonglong2 h01 = sh[rr * 4 + 0];
        ulonglong2 h23 = sh[rr * 4 + 1];
        ulonglong2 h45 = sh[rr * 4 + 2];
        ulonglong2 h67 = sh[rr * 4 + 3];

        unsigned long long a0 = bb0, a1 = bb1;
        a0 = ffma2(h01.x, w[0][0], a0);  a1 = ffma2(h01.x, w[0][1], a1);
        a0 = ffma2(h01.y, w[1][0], a0);  a1 = ffma2(h01.y, w[1][1], a1);
        a0 = ffma2(h23.x, w[2][0], a0);  a1 = ffma2(h23.x, w[2][1], a1);
        a0 = ffma2(h23.y, w[3][0], a0);  a1 = ffma2(h23.y, w[3][1], a1);
        a0 = ffma2(h45.x, w[4][0], a0);  a1 = ffma2(h45.x, w[4][1], a1);
        a0 = ffma2(h45.y, w[5][0], a0);  a1 = ffma2(h45.y, w[5][1], a1);
        a0 = ffma2(h67.x, w[6][0], a0);  a1 = ffma2(h67.x, w[6][1], a1);
        a0 = ffma2(h67.y, w[7][0], a0);  a1 = ffma2(h67.y, w[7][1], a1);

        float f0, f1, f2, f3;
        unpack2(a0, f0, f1);
        unpack2(a1, f2, f3);
        __stcs((float4*)(outp + (size_t)rr * 784),
               make_float4(sigmoidf_fast(f0), sigmoidf_fast(f1),
                           sigmoidf_fast(f2), sigmoidf_fast(f3)));
    }
}

// ---------------------------------------------------------------------------
extern "C" void kernel_launch(void* const* d_in, const int* in_sizes, int n_in,
                              void* d_out, int out_size) {
    const float* z     = (const float*)d_in[0];
    const float* W_in  = (const float*)d_in[1];
    const float* b_in  = (const float*)d_in[2];
    const float* theta = (const float*)d_in[3];
    const float* W1    = (const float*)d_in[4];
    const float* b1    = (const float*)d_in[5];
    const float* W2    = (const float*)d_in[6];
    const float* b2    = (const float*)d_in[7];

    int B = in_sizes[0] / 128;          // 65536
    qd_front_kernel<<<B / 128, 128>>>(z, W_in, b_in, theta, W1, b1);
    qd_gemm_kernel<<<B / ROWS_PER_BLOCK, 224>>>(W2, b2, (float*)d_out);
}